// round 5
// baseline (speedup 1.0000x reference)
#include <cuda_runtime.h>
#include <cstdint>
#include <cstddef>

// Problem constants
#define NB   512
#define NT   2048
#define NXD  32
#define NUD  8
#define NYD  16
#define NH   128
#define NTHD 4
#define ZF_DIM 44   // NXD + NUD + NTHD
#define ZH_DIM 36   // NXD + NTHD

#define THREADS 256   // 2 batch rows per block, 128 threads (4 warps) each

// ---- shared memory layout (float offsets) ----
// Weights stored in natural row-major so that the per-output accumulation
// walks k ascending: W1[k*128 + j], W2[k*NOUT + i].
#define OFF_WF1   0                      // 44*128 = 5632
#define OFF_WF2   (OFF_WF1 + 5632)       // 128*32 = 4096
#define OFF_WH1   (OFF_WF2 + 4096)       // 36*128 = 4608
#define OFF_WH2   (OFF_WH1 + 4608)       // 128*16 = 2048
#define OFF_BF1   (OFF_WH2 + 2048)       // 128
#define OFF_BF2   (OFF_BF1 + 128)        // 32
#define OFF_BH1   (OFF_BF2 + 32)         // 128
#define OFF_BH2   (OFF_BH1 + 128)        // 16
#define OFF_ROWS  (OFF_BH2 + 16)
// per-row area: zf[48] | zh[2][40] | hf[128] | hh[128]  = 384 floats
#define ROW_STRIDE 384
#define SMEM_FLOATS (OFF_ROWS + 2*ROW_STRIDE)
#define SMEM_BYTES  (SMEM_FLOATS * 4)    // ~69.9 KB

// Exact XLA EmitFastTanh (Eigen generic_fast_tanh_float constants) — what
// jnp.tanh lowers to for f32 on XLA CPU (and GPU). Every op IEEE rn.
__device__ __forceinline__ float xla_tanh(float x) {
    const float kClamp = 7.90531110763549805f;
    float ax = fabsf(x);
    float xc = fminf(fmaxf(x, -kClamp), kClamp);
    float x2 = __fmul_rn(xc, xc);
    float p;
    p = __fmaf_rn(x2, -2.76076847742355e-16f, 2.00018790482477e-13f);
    p = __fmaf_rn(x2, p, -8.60467152213735e-11f);
    p = __fmaf_rn(x2, p,  5.12229709037114e-08f);
    p = __fmaf_rn(x2, p,  1.48572235717979e-05f);
    p = __fmaf_rn(x2, p,  6.37261928875436e-04f);
    p = __fmaf_rn(x2, p,  4.89352455891786e-03f);
    p = __fmul_rn(xc, p);
    float q;
    q = __fmaf_rn(x2, 1.19825839466702e-06f, 1.18534705686654e-04f);
    q = __fmaf_rn(x2, q, 2.26843463243900e-03f);
    q = __fmaf_rn(x2, q, 4.89352518554385e-03f);
    float r = __fdiv_rn(p, q);
    return (ax < 0.0004f) ? x : r;
}

// Strictly-ordered dot: single accumulator, k ascending, one IEEE FMA per k.
// This matches Eigen gebp / SIMT sgemm per-output accumulation order.
template<int K, int LD>
__device__ __forceinline__ float dot_seq(const float* __restrict__ z,
                                         const float* __restrict__ W, int j) {
    float acc = 0.f;
#pragma unroll
    for (int k = 0; k < K; k++)
        acc = __fmaf_rn(z[k], W[k * LD + j], acc);
    return acc;
}

// Named barriers, per-row (half):  A = all 4 warps (128), B = warps 0-1 (64),
// C = warps 2-3 (64).
#define BAR_A() asm volatile("bar.sync %0, 128;" :: "r"(1 + half * 3) : "memory")
#define BAR_B() asm volatile("bar.sync %0, 64;"  :: "r"(2 + half * 3) : "memory")
#define BAR_C() asm volatile("bar.sync %0, 64;"  :: "r"(3 + half * 3) : "memory")

__global__ void __launch_bounds__(THREADS, 2)
ssm_kernel(const float* __restrict__ x0g, const float* __restrict__ ug,
           const float* __restrict__ thfg, const float* __restrict__ thhg,
           const float* __restrict__ Wf1g, const float* __restrict__ bf1g,
           const float* __restrict__ Wf2g, const float* __restrict__ bf2g,
           const float* __restrict__ Wh1g, const float* __restrict__ bh1g,
           const float* __restrict__ Wh2g, const float* __restrict__ bh2g,
           const float* __restrict__ xming, const float* __restrict__ xmaxg,
           const float* __restrict__ yming, const float* __restrict__ ymaxg,
           float* __restrict__ outx, float* __restrict__ outy)
{
    extern __shared__ float sm[];
    const int tid  = threadIdx.x;
    const int half = tid >> 7;       // batch row within the block
    const int tt   = tid & 127;      // thread within the row team
    const int w    = tt >> 5;        // warp-in-row 0..3
    const int lane = tt & 31;
    const int b    = blockIdx.x * 2 + half;

    // ---- weight staging: exact copies, natural layout ----
    for (int e = tid; e < ZF_DIM * NH; e += THREADS) sm[OFF_WF1 + e] = Wf1g[e];
    for (int e = tid; e < NH * NXD;  e += THREADS) sm[OFF_WF2 + e] = Wf2g[e];
    for (int e = tid; e < ZH_DIM * NH; e += THREADS) sm[OFF_WH1 + e] = Wh1g[e];
    for (int e = tid; e < NH * NYD;  e += THREADS) sm[OFF_WH2 + e] = Wh2g[e];
    if (tid < 128) sm[OFF_BF1 + tid] = bf1g[tid];
    else           sm[OFF_BH1 + (tid - 128)] = bh1g[tid - 128];
    if (tid < 32)       sm[OFF_BF2 + tid] = bf2g[tid];
    else if (tid < 48)  sm[OFF_BH2 + (tid - 32)] = bh2g[tid - 32];

    const float* WF1 = sm + OFF_WF1;
    const float* WF2 = sm + OFF_WF2;
    const float* WH1 = sm + OFF_WH1;
    const float* WH2 = sm + OFF_WH2;

    float* zf  = sm + OFF_ROWS + half * ROW_STRIDE;  // [x(32)|u(8)|thf(4)|pad]
    float* zh0 = zf + 48;    // h input buffer 0: [x_pre(32)|thh(4)|pad]
    float* zh1 = zh0 + 40;   // h input buffer 1
    float* hf  = zh1 + 40;   // f hidden (tanh outputs), 128
    float* hh  = hf + 128;   // h hidden, 128
    float* zhbuf[2] = { zh0, zh1 };

    const float xlo = xming[0], xhi = xmaxg[0];
    const float ylo = yming[0], yhi = ymaxg[0];

    const float* ub  = ug   + (size_t)b * NT * NUD;
    float*       oxb = outx + (size_t)b * NT * NXD;
    float*       oyb = outy + (size_t)b * NT * NYD;

    // ---- per-row init ----
    if (tt < 32) {
        float xv = x0g[b * 32 + tt];
        zf[tt]  = xv;           // x carry (exact)
        zh1[tt] = xv;           // y0 = h(x_0) uses buffer 1
        oxb[tt] = xv;           // x output at t=0 is x_0
    }
    if (tt >= 32 && tt < 44) {
        int r = tt - 32;
        zf[tt] = (r < 8) ? ub[r] : thfg[b * 4 + (r - 8)];   // u_0 | theta_f
    }
    if (tt < 4) {
        float th = thhg[b * 4 + tt];
        zh0[32 + tt] = th;      // theta_h constant in both buffers
        zh1[32 + tt] = th;
    }
    __syncthreads();

    // ===================== main rollout =====================
    // Warps 0-1: f-MLP critical path for step t.
    // Warps 2-3: h-MLP for step t-1 (t=0 handles y0 = h(x_0) from zh1).
    // Step t writes x output index t+1; h of step s writes y index s+1.
    for (int t = 0; t < NT - 1; t++) {
        if (w < 2) {
            // -- prefetch u_{t+1} early (latency hidden under f1+f2) --
            float ureg = 0.f;
            if (w == 1) {
                if (lane < 8) ureg = ub[(size_t)(t + 1) * NUD + lane];
                if (lane == 0 && t + 8 < NT)
                    asm volatile("prefetch.global.L2 [%0];" :: "l"(ub + (size_t)(t + 8) * NUD));
            }
            // -- f1: hidden units j and j+64, strict 44-chains --
            int j = w * 32 + lane;
            float a0 = dot_seq<ZF_DIM, NH>(zf, WF1, j);
            float a1 = dot_seq<ZF_DIM, NH>(zf, WF1, j + 64);
            hf[j]      = xla_tanh(__fadd_rn(a0, sm[OFF_BF1 + j]));
            hf[j + 64] = xla_tanh(__fadd_rn(a1, sm[OFF_BF1 + j + 64]));
            BAR_B();
            if (w == 0) {
                // -- f2: one strict 128-chain per output lane --
                float acc = dot_seq<NH, NXD>(hf, WF2, lane);
                float dx  = __fadd_rn(acc, sm[OFF_BF2 + lane]);
                float xn  = __fadd_rn(zf[lane], dx);     // pre-clamp x_new
                zhbuf[t & 1][lane] = xn;                 // h input for step t
                float xc = fminf(fmaxf(xn, xlo), xhi);
                zf[lane] = xc;                           // clamped carry
                oxb[(size_t)(t + 1) * NXD + lane] = xc;
            } else {
                if (lane < 8) zf[32 + lane] = ureg;      // stage u_{t+1}
            }
        } else {
            // -- h side: process step t-1 (or y0 prologue at t=0) --
            const float* zh = (t == 0) ? zh1 : zhbuf[(t - 1) & 1];
            int j = (w - 2) * 32 + lane;
            float a0 = dot_seq<ZH_DIM, NH>(zh, WH1, j);
            float a1 = dot_seq<ZH_DIM, NH>(zh, WH1, j + 64);
            hh[j]      = xla_tanh(__fadd_rn(a0, sm[OFF_BH1 + j]));
            hh[j + 64] = xla_tanh(__fadd_rn(a1, sm[OFF_BH1 + j + 64]));
            BAR_C();
            if (w == 2 && lane < 16) {
                float acc = dot_seq<NH, NYD>(hh, WH2, lane);
                float y   = __fadd_rn(acc, sm[OFF_BH2 + lane]);
                if (t > 0) y = fminf(fmaxf(y, ylo), yhi);   // y0 is unclamped
                oyb[(size_t)t * NYD + lane] = y;
            }
        }
        BAR_A();
    }

    // ---- epilogue: h for the final step (s = NT-2) -> y index NT-1 ----
    if (w >= 2) {
        const float* zh = zhbuf[(NT - 2) & 1];
        int j = (w - 2) * 32 + lane;
        float a0 = dot_seq<ZH_DIM, NH>(zh, WH1, j);
        float a1 = dot_seq<ZH_DIM, NH>(zh, WH1, j + 64);
        hh[j]      = xla_tanh(__fadd_rn(a0, sm[OFF_BH1 + j]));
        hh[j + 64] = xla_tanh(__fadd_rn(a1, sm[OFF_BH1 + j + 64]));
        BAR_C();
        if (w == 2 && lane < 16) {
            float acc = dot_seq<NH, NYD>(hh, WH2, lane);
            float y   = __fadd_rn(acc, sm[OFF_BH2 + lane]);
            y = fminf(fmaxf(y, ylo), yhi);
            oyb[(size_t)(NT - 1) * NYD + lane] = y;
        }
    }
}

extern "C" void kernel_launch(void* const* d_in, const int* in_sizes, int n_in,
                              void* d_out, int out_size) {
    (void)in_sizes; (void)n_in; (void)out_size;
    cudaFuncSetAttribute(ssm_kernel, cudaFuncAttributeMaxDynamicSharedMemorySize, SMEM_BYTES);

    const float* x0   = (const float*)d_in[0];
    const float* u    = (const float*)d_in[1];
    const float* thf  = (const float*)d_in[2];
    const float* thh  = (const float*)d_in[3];
    const float* Wf1  = (const float*)d_in[4];
    const float* bf1  = (const float*)d_in[5];
    const float* Wf2  = (const float*)d_in[6];
    const float* bf2  = (const float*)d_in[7];
    const float* Wh1  = (const float*)d_in[8];
    const float* bh1  = (const float*)d_in[9];
    const float* Wh2  = (const float*)d_in[10];
    const float* bh2  = (const float*)d_in[11];
    const float* xmin = (const float*)d_in[12];
    const float* xmax = (const float*)d_in[13];
    const float* ymin = (const float*)d_in[14];
    const float* ymax = (const float*)d_in[15];

    float* outx = (float*)d_out;
    float* outy = outx + (size_t)NB * NT * NXD;

    ssm_kernel<<<NB / 2, THREADS, SMEM_BYTES>>>(
        x0, u, thf, thh, Wf1, bf1, Wf2, bf2, Wh1, bh1, Wh2, bh2,
        xmin, xmax, ymin, ymax, outx, outy);
}

// round 7
// speedup vs baseline: 1.3676x; 1.3676x over previous
#include <cuda_runtime.h>
#include <cstdint>
#include <cstddef>

// Problem constants
#define NB   512
#define NT   2048
#define NXD  32
#define NUD  8
#define NYD  16
#define NH   128
#define NTHD 4
#define ZF_DIM 44   // NXD + NUD + NTHD
#define ZH_DIM 36   // NXD + NTHD

#define THREADS 128   // 1 batch row per block, 4 warps

// Exact XLA EmitFastTanh — bitwise-matched to the reference (verified rel_err=0).
__device__ __forceinline__ float xla_tanh(float x) {
    const float kClamp = 7.90531110763549805f;
    float ax = fabsf(x);
    float xc = fminf(fmaxf(x, -kClamp), kClamp);
    float x2 = __fmul_rn(xc, xc);
    float p;
    p = __fmaf_rn(x2, -2.76076847742355e-16f, 2.00018790482477e-13f);
    p = __fmaf_rn(x2, p, -8.60467152213735e-11f);
    p = __fmaf_rn(x2, p,  5.12229709037114e-08f);
    p = __fmaf_rn(x2, p,  1.48572235717979e-05f);
    p = __fmaf_rn(x2, p,  6.37261928875436e-04f);
    p = __fmaf_rn(x2, p,  4.89352455891786e-03f);
    p = __fmul_rn(xc, p);
    float q;
    q = __fmaf_rn(x2, 1.19825839466702e-06f, 1.18534705686654e-04f);
    q = __fmaf_rn(x2, q, 2.26843463243900e-03f);
    q = __fmaf_rn(x2, q, 4.89352518554385e-03f);
    float r = __fdiv_rn(p, q);
    return (ax < 0.0004f) ? x : r;
}

// Named sub-barriers: 1 = f-side (warps 0-1, 64 thr), 2 = h-side (warps 2-3).
#define BAR_F() asm volatile("bar.sync 1, 64;" ::: "memory")
#define BAR_H() asm volatile("bar.sync 2, 64;" ::: "memory")

__global__ void __launch_bounds__(THREADS, 4)
ssm_kernel(const float* __restrict__ x0g, const float* __restrict__ ug,
           const float* __restrict__ thfg, const float* __restrict__ thhg,
           const float* __restrict__ Wf1g, const float* __restrict__ bf1g,
           const float* __restrict__ Wf2g, const float* __restrict__ bf2g,
           const float* __restrict__ Wh1g, const float* __restrict__ bh1g,
           const float* __restrict__ Wh2g, const float* __restrict__ bh2g,
           const float* __restrict__ xming, const float* __restrict__ xmaxg,
           const float* __restrict__ yming, const float* __restrict__ ymaxg,
           float* __restrict__ outx, float* __restrict__ outy)
{
    // Static shared: transposed layer-2 weights (conflict-free LDS.128 rows),
    // activation buffers, ping-pong state.
    __shared__ __align__(16) float WF2T[NXD * 132];   // WF2T[i*132+k] = Wf2[k][i]
    __shared__ __align__(16) float WH2T[NYD * 132];   // WH2T[i*132+k] = Wh2[k][i]
    __shared__ __align__(16) float hf[NH], hh[NH];
    __shared__ __align__(16) float zf0[48], zf1[48];  // [x(32)|u(8)|thf(4)|0-pad]
    __shared__ __align__(16) float zh0[48], zh1[48];  // [x_pre(32)|thh(4)|0-pad]

    const int tt   = threadIdx.x;
    const int w    = tt >> 5;
    const int lane = tt & 31;
    const int b    = blockIdx.x;

    const float* ub  = ug   + (size_t)b * NT * NUD;
    float*       oxb = outx + (size_t)b * NT * NXD;
    float*       oyb = outy + (size_t)b * NT * NYD;

    // ---- layer-1 weights into REGISTERS (per-thread columns, loop-invariant) ----
    float wA[ZF_DIM], wB[ZF_DIM];
    float bA, bB;
    if (tt < 64) {
#pragma unroll
        for (int k = 0; k < ZF_DIM; k++) {
            wA[k] = Wf1g[k * NH + tt];
            wB[k] = Wf1g[k * NH + 64 + tt];
        }
        bA = bf1g[tt];
        bB = bf1g[64 + tt];
    } else {
        const int j = tt - 64;
#pragma unroll
        for (int k = 0; k < ZH_DIM; k++) {
            wA[k] = Wh1g[k * NH + j];
            wB[k] = Wh1g[k * NH + 64 + j];
        }
        bA = bh1g[j];
        bB = bh1g[64 + j];
    }
    const float bf2v = bf2g[lane];            // used by warp 0
    const float bh2v = bh2g[lane & 15];       // used by warp 2
    const float xlo = xming[0], xhi = xmaxg[0];
    const float ylo = yming[0], yhi = ymaxg[0];

    // ---- stage transposed layer-2 weights ----
    for (int e = tt; e < NH * NXD; e += THREADS) {
        int k = e >> 5, i = e & 31;
        WF2T[i * 132 + k] = Wf2g[e];
    }
    for (int e = tt; e < NH * NYD; e += THREADS) {
        int k = e >> 4, i = e & 15;
        WH2T[i * 132 + k] = Wh2g[e];
    }

    // ---- state init ----
    if (tt < 32) {
        float xv = x0g[b * 32 + tt];
        zf0[tt] = xv;          // step 0 reads buffer 0
        zh1[tt] = xv;          // y0 = h(x_0): h at t=0 reads buffer 1
        oxb[tt] = xv;          // x output index 0 is x_0
    }
    if (tt >= 32 && tt < 48) {
        int r = tt - 32;
        float v = 0.f;
        if (r < 8)       v = ub[r];                 // u_0
        else if (r < 12) v = thfg[b * 4 + (r - 8)]; // theta_f
        zf0[tt] = v;
        zf1[tt] = (r < 8) ? 0.f : v;   // u slot of buf1 written at t=0
    }
    if (tt < 4) {
        float th = thhg[b * 4 + tt];
        zh0[32 + tt] = th;
        zh1[32 + tt] = th;
    }
    if (tt >= 36 && tt < 48) { zh0[tt] = 0.f; zh1[tt] = 0.f; }
    __syncthreads();

    // ===================== main rollout =====================
    // f-side (w0,w1): step t.  h-side (w2,w3): step t-1 (y0 prologue at t=0).
    for (int t = 0; t < NT - 1; t++) {
        if (tt < 64) {
            const float* zc = (t & 1) ? zf1 : zf0;
            // -- f1: strict ascending-k 44-chains, weights from regs --
            float a0 = 0.f, a1 = 0.f;
#pragma unroll
            for (int q = 0; q < ZF_DIM / 4; q++) {
                float4 z4 = *(const float4*)(zc + 4 * q);
                a0 = __fmaf_rn(z4.x, wA[4 * q + 0], a0);
                a1 = __fmaf_rn(z4.x, wB[4 * q + 0], a1);
                a0 = __fmaf_rn(z4.y, wA[4 * q + 1], a0);
                a1 = __fmaf_rn(z4.y, wB[4 * q + 1], a1);
                a0 = __fmaf_rn(z4.z, wA[4 * q + 2], a0);
                a1 = __fmaf_rn(z4.z, wB[4 * q + 2], a1);
                a0 = __fmaf_rn(z4.w, wA[4 * q + 3], a0);
                a1 = __fmaf_rn(z4.w, wB[4 * q + 3], a1);
            }
            hf[tt]      = xla_tanh(__fadd_rn(a0, bA));
            hf[tt + 64] = xla_tanh(__fadd_rn(a1, bB));
            BAR_F();
            if (w == 0) {
                // -- f2: strict 128-chain, transposed smem weights, vector loads --
                float acc = 0.f;
                const float* wr = WF2T + lane * 132;
#pragma unroll
                for (int q = 0; q < NH / 4; q++) {
                    float4 h4 = *(const float4*)(hf + 4 * q);
                    float4 w4 = *(const float4*)(wr + 4 * q);
                    acc = __fmaf_rn(h4.x, w4.x, acc);
                    acc = __fmaf_rn(h4.y, w4.y, acc);
                    acc = __fmaf_rn(h4.z, w4.z, acc);
                    acc = __fmaf_rn(h4.w, w4.w, acc);
                }
                float dx = __fadd_rn(acc, bf2v);
                float xn = __fadd_rn(zc[lane], dx);       // pre-clamp x_new
                ((t & 1) ? zh1 : zh0)[lane] = xn;         // h input for step t
                float xc = fminf(fmaxf(xn, xlo), xhi);
                ((t & 1) ? zf0 : zf1)[lane] = xc;         // carry -> next buffer
                oxb[(size_t)(t + 1) * NXD + lane] = xc;
            }
        } else {
            // -- h-side: step t-1, input buffer (t+1)&1 --
            float ureg = 0.f;
            if (w == 3) {
                if (lane < 8) ureg = ub[(size_t)(t + 1) * NUD + lane];
                if (lane == 0 && t + 8 < NT)
                    asm volatile("prefetch.global.L2 [%0];" :: "l"(ub + (size_t)(t + 8) * NUD));
            }
            const float* zh = (t & 1) ? zh0 : zh1;
            const int j = tt - 64;
            float a0 = 0.f, a1 = 0.f;
#pragma unroll
            for (int q = 0; q < ZH_DIM / 4; q++) {
                float4 z4 = *(const float4*)(zh + 4 * q);
                a0 = __fmaf_rn(z4.x, wA[4 * q + 0], a0);
                a1 = __fmaf_rn(z4.x, wB[4 * q + 0], a1);
                a0 = __fmaf_rn(z4.y, wA[4 * q + 1], a0);
                a1 = __fmaf_rn(z4.y, wB[4 * q + 1], a1);
                a0 = __fmaf_rn(z4.z, wA[4 * q + 2], a0);
                a1 = __fmaf_rn(z4.z, wB[4 * q + 2], a1);
                a0 = __fmaf_rn(z4.w, wA[4 * q + 3], a0);
                a1 = __fmaf_rn(z4.w, wB[4 * q + 3], a1);
            }
            hh[j]      = xla_tanh(__fadd_rn(a0, bA));
            hh[j + 64] = xla_tanh(__fadd_rn(a1, bB));
            BAR_H();
            if (w == 2 && lane < 16) {
                float acc = 0.f;
                const float* wr = WH2T + lane * 132;
#pragma unroll
                for (int q = 0; q < NH / 4; q++) {
                    float4 h4 = *(const float4*)(hh + 4 * q);
                    float4 w4 = *(const float4*)(wr + 4 * q);
                    acc = __fmaf_rn(h4.x, w4.x, acc);
                    acc = __fmaf_rn(h4.y, w4.y, acc);
                    acc = __fmaf_rn(h4.z, w4.z, acc);
                    acc = __fmaf_rn(h4.w, w4.w, acc);
                }
                float y = __fadd_rn(acc, bh2v);
                if (t > 0) y = fminf(fmaxf(y, ylo), yhi);  // y0 unclamped
                oyb[(size_t)t * NYD + lane] = y;
            }
            if (w == 3 && lane < 8)
                ((t & 1) ? zf0 : zf1)[32 + lane] = ureg;   // stage u_{t+1}
        }
        __syncthreads();
    }

    // ---- epilogue: h for step NT-2 -> y index NT-1 ----
    if (tt >= 64) {
        const float* zh = ((NT - 2) & 1) ? zh1 : zh0;
        const int j = tt - 64;
        float a0 = 0.f, a1 = 0.f;
#pragma unroll
        for (int q = 0; q < ZH_DIM / 4; q++) {
            float4 z4 = *(const float4*)(zh + 4 * q);
            a0 = __fmaf_rn(z4.x, wA[4 * q + 0], a0);
            a1 = __fmaf_rn(z4.x, wB[4 * q + 0], a1);
            a0 = __fmaf_rn(z4.y, wA[4 * q + 1], a0);
            a1 = __fmaf_rn(z4.y, wB[4 * q + 1], a1);
            a0 = __fmaf_rn(z4.z, wA[4 * q + 2], a0);
            a1 = __fmaf_rn(z4.z, wB[4 * q + 2], a1);
            a0 = __fmaf_rn(z4.w, wA[4 * q + 3], a0);
            a1 = __fmaf_rn(z4.w, wB[4 * q + 3], a1);
        }
        hh[j]      = xla_tanh(__fadd_rn(a0, bA));
        hh[j + 64] = xla_tanh(__fadd_rn(a1, bB));
        BAR_H();
        if (w == 2 && lane < 16) {
            float acc = 0.f;
            const float* wr = WH2T + lane * 132;
#pragma unroll
            for (int q = 0; q < NH / 4; q++) {
                float4 h4 = *(const float4*)(hh + 4 * q);
                float4 w4 = *(const float4*)(wr + 4 * q);
                acc = __fmaf_rn(h4.x, w4.x, acc);
                acc = __fmaf_rn(h4.y, w4.y, acc);
                acc = __fmaf_rn(h4.z, w4.z, acc);
                acc = __fmaf_rn(h4.w, w4.w, acc);
            }
            float y = __fadd_rn(acc, bh2v);
            y = fminf(fmaxf(y, ylo), yhi);
            oyb[(size_t)(NT - 1) * NYD + lane] = y;
        }
    }
}

extern "C" void kernel_launch(void* const* d_in, const int* in_sizes, int n_in,
                              void* d_out, int out_size) {
    (void)in_sizes; (void)n_in; (void)out_size;

    const float* x0   = (const float*)d_in[0];
    const float* u    = (const float*)d_in[1];
    const float* thf  = (const float*)d_in[2];
    const float* thh  = (const float*)d_in[3];
    const float* Wf1  = (const float*)d_in[4];
    const float* bf1  = (const float*)d_in[5];
    const float* Wf2  = (const float*)d_in[6];
    const float* bf2  = (const float*)d_in[7];
    const float* Wh1  = (const float*)d_in[8];
    const float* bh1  = (const float*)d_in[9];
    const float* Wh2  = (const float*)d_in[10];
    const float* bh2  = (const float*)d_in[11];
    const float* xmin = (const float*)d_in[12];
    const float* xmax = (const float*)d_in[13];
    const float* ymin = (const float*)d_in[14];
    const float* ymax = (const float*)d_in[15];

    float* outx = (float*)d_out;
    float* outy = outx + (size_t)NB * NT * NXD;

    ssm_kernel<<<NB, THREADS>>>(
        x0, u, thf, thh, Wf1, bf1, Wf2, bf2, Wh1, bh1, Wh2, bh2,
        xmin, xmax, ymin, ymax, outx, outy);
}